// round 13
// baseline (speedup 1.0000x reference)
#include <cuda_runtime.h>
#include <cuda_fp16.h>
#include <cstdint>

#define BATCH 8
#define NN    2048
#define CC    128
#define EPSV  0.1f
#define NUNITS (BATCH * (NN / 64))      // 256 work units (64 i-rows each)

// Scratch (static device globals — no runtime allocation)
__device__ __half g_hT[BATCH * 64 * CC * 32];     // blocked hT [b][ktb][o][jj] fp16 (jj=32)
__device__ float  g_al[BATCH * NN];
__device__ float  g_ar[BATCH * NN];
__device__ int    g_work;                          // persistent work counter

// ---------------------------------------------------------------- helpers --
__device__ __forceinline__ float tanh_fast(float x) {
    float y; asm("tanh.approx.f32 %0, %1;" : "=f"(y) : "f"(x)); return y;
}
__device__ __forceinline__ uint32_t f2h2(float lo, float hi) {
    __half2 h = __floats2half2_rn(lo, hi);
    return *(uint32_t*)&h;
}
__device__ __forceinline__ uint32_t smem_u32(const void* p) {
    uint32_t a;
    asm("{ .reg .u64 t; cvta.to.shared.u64 t, %1; cvt.u32.u64 %0, t; }" : "=r"(a) : "l"(p));
    return a;
}
// fp16 MMA m16n8k16
__device__ __forceinline__ void mma_f16(float* d, const uint32_t* a, uint32_t b0, uint32_t b1) {
    asm volatile(
        "mma.sync.aligned.m16n8k16.row.col.f32.f16.f16.f32 "
        "{%0,%1,%2,%3}, {%4,%5,%6,%7}, {%8,%9}, {%0,%1,%2,%3};"
        : "+f"(d[0]), "+f"(d[1]), "+f"(d[2]), "+f"(d[3])
        : "r"(a[0]), "r"(a[1]), "r"(a[2]), "r"(a[3]), "r"(b0), "r"(b1));
}
__device__ __forceinline__ void ldmatrix_x4(uint32_t& r0, uint32_t& r1,
                                            uint32_t& r2, uint32_t& r3, uint32_t addr) {
    asm volatile("ldmatrix.sync.aligned.m8n8.x4.shared.b16 {%0,%1,%2,%3}, [%4];"
                 : "=r"(r0), "=r"(r1), "=r"(r2), "=r"(r3) : "r"(addr));
}
#define CP_ASYNC16(dst, src) \
    asm volatile("cp.async.cg.shared.global [%0], [%1], 16;" :: "r"(dst), "l"(src))
#define CP_COMMIT()  asm volatile("cp.async.commit_group;" ::: "memory")
#define CP_WAIT0()   asm volatile("cp.async.wait_group 0;" ::: "memory")

// ---------------------------------------------------------------------------
// Kernel 1 (prep): h = x @ W via fp16 mma. 256 blocks x 64 rows (occ 3-4).
// Epilogue: alpha_l/alpha_r dots + blocked hT store. Resets work counter.
// ---------------------------------------------------------------------------
#define PX_W 68
#define PREP_SMEM_BYTES ((64 * PX_W + 128 * PX_W + 256) * 4)   // 53248 B

__global__ void __launch_bounds__(256, 2)
prep_tensor(const float* __restrict__ x, const float* __restrict__ W,
            const float* __restrict__ wl, const float* __restrict__ wr) {
    extern __shared__ __align__(16) uint32_t sm[];
    uint32_t* sX  = sm;                        // [64][68] words (x fp16, then h fp16)
    uint32_t* sW  = sm + 64 * PX_W;            // [128 o][68] words (W^T fp16)
    float*    swl = (float*)(sm + 64 * PX_W + 128 * PX_W);
    float*    swr = swl + 128;
    __half*   sWh = (__half*)sW;

    const int tid  = threadIdx.x;
    const int w    = tid >> 5;
    const int lane = tid & 31;
    const int fr   = lane >> 2;
    const int fc   = lane & 3;
    const int b    = blockIdx.x >> 5;
    const int j0   = (blockIdx.x & 31) * 64;
    const int r0   = blockIdx.x * 64;          // == b*NN + j0

    if (blockIdx.x == 0 && tid == 0) g_work = 0;   // reset persistent counter

    if (tid < 128) { swl[tid] = wl[tid]; swr[tid] = wr[tid]; }

    // stage x tile [64][128] fp32 -> fp16
#pragma unroll
    for (int e = 0; e < 8; e++) {
        const int idx = e * 256 + tid;         // 0..2047 float4
        const int row = idx >> 5;
        const int c4  = (idx & 31) * 4;
        const float4 v = *(const float4*)&x[(size_t)(r0 + row) * CC + c4];
        uint2 p; p.x = f2h2(v.x, v.y); p.y = f2h2(v.z, v.w);
        *(uint2*)&sX[row * PX_W + (idx & 31) * 2] = p;
    }
    // stage W^T in-block: read W [k][o] fp32 coalesced, scatter fp16 transposed
#pragma unroll
    for (int e = 0; e < 16; e++) {
        const int idx = e * 256 + tid;
        const int k   = idx >> 5;
        const int o4  = (idx & 31) * 4;
        const float4 v = *(const float4*)&W[(size_t)k * CC + o4];
        sWh[(size_t)(o4 + 0) * 136 + k] = __float2half_rn(v.x);
        sWh[(size_t)(o4 + 1) * 136 + k] = __float2half_rn(v.y);
        sWh[(size_t)(o4 + 2) * 136 + k] = __float2half_rn(v.z);
        sWh[(size_t)(o4 + 3) * 136 + k] = __float2half_rn(v.w);
    }
    __syncthreads();

    // MMA: warp tile 16 rows x 64 cols; wm = (w&3)*16, wn = (w>>2)*64
    const int wm = (w & 3) * 16;
    const int wn = (w >> 2) * 64;
    float acc[8][4];
#pragma unroll
    for (int nt = 0; nt < 8; nt++)
#pragma unroll
        for (int c = 0; c < 4; c++) acc[nt][c] = 0.0f;

#pragma unroll
    for (int ks = 0; ks < 8; ks++) {
        uint32_t af[4];
        const int abase = (wm + fr) * PX_W + ks * 8 + fc;
        af[0] = sX[abase];
        af[1] = sX[abase + 8 * PX_W];
        af[2] = sX[abase + 4];
        af[3] = sX[abase + 8 * PX_W + 4];
#pragma unroll
        for (int nt = 0; nt < 8; nt++) {
            const int bbase = (wn + nt * 8 + fr) * PX_W + ks * 8 + fc;
            mma_f16(acc[nt], af, sW[bbase], sW[bbase + 4]);
        }
    }
    __syncthreads();

    // dump h (fp16) into sX region: [row j][o], word col = o/2
#pragma unroll
    for (int nt = 0; nt < 8; nt++) {
        sX[(wm + fr)     * PX_W + wn / 2 + nt * 4 + fc] = f2h2(acc[nt][0], acc[nt][1]);
        sX[(wm + fr + 8) * PX_W + wn / 2 + nt * 4 + fc] = f2h2(acc[nt][2], acc[nt][3]);
    }
    __syncthreads();

    const __half* sH = (const __half*)sX;      // [j][o] stride 136 halfs

    // blocked hT store: thread -> o = tid>>1, jh = tid&1 (32 j each)
    {
        const int o  = tid >> 1;
        const int jh = tid & 1;
        const int kt = (j0 >> 5) + jh;
        uint32_t wbuf[16];
#pragma unroll
        for (int r2 = 0; r2 < 16; r2++) {
            const int j = jh * 32 + r2 * 2;
            const __half h0 = sH[(size_t)j * 136 + o];
            const __half h1 = sH[(size_t)(j + 1) * 136 + o];
            wbuf[r2] = (uint32_t)__half_as_ushort(h0) | ((uint32_t)__half_as_ushort(h1) << 16);
        }
        uint4* dst = (uint4*)(g_hT + ((size_t)((b * 64 + kt) * 128 + o)) * 32);
        dst[0] = make_uint4(wbuf[0],  wbuf[1],  wbuf[2],  wbuf[3]);
        dst[1] = make_uint4(wbuf[4],  wbuf[5],  wbuf[6],  wbuf[7]);
        dst[2] = make_uint4(wbuf[8],  wbuf[9],  wbuf[10], wbuf[11]);
        dst[3] = make_uint4(wbuf[12], wbuf[13], wbuf[14], wbuf[15]);
    }

    // alpha_l / alpha_r dots: 4 threads per row (oh = tid&3, 32 o's each)
    {
        const int r  = tid >> 2;
        const int oh = tid & 3;
        float pl = 0.0f, pr = 0.0f;
#pragma unroll
        for (int w2 = 0; w2 < 16; w2++) {
            const uint32_t wd = ((const uint32_t*)sH)[r * PX_W + oh * 16 + w2];
            const __half2 hh = *(const __half2*)&wd;
            const float2 f = __half22float2(hh);
            const int o0 = oh * 32 + w2 * 2;
            pl += f.x * swl[o0] + f.y * swl[o0 + 1];
            pr += f.x * swr[o0] + f.y * swr[o0 + 1];
        }
        pl += __shfl_xor_sync(0xffffffffu, pl, 1);
        pr += __shfl_xor_sync(0xffffffffu, pr, 1);
        pl += __shfl_xor_sync(0xffffffffu, pl, 2);
        pr += __shfl_xor_sync(0xffffffffu, pr, 2);
        if (oh == 0) {
            g_al[b * NN + j0 + r] = pl;
            g_ar[b * NN + j0 + r] = pr;
        }
    }
}

// ---------------------------------------------------------------------------
// Kernel 2 (main): persistent work-stealing CTAs. Unit = 64 i x 128 o.
// Warp tile 32 i x 32 o (8 warps). KC=64, double-buffered A (built) and
// B (cp.async). adj: register prefetch fetched at body start. (R12, frozen)
// ---------------------------------------------------------------------------
#define KC 64
#define KT (NN / KC)                    // 32
#define SA_W 36
#define SB_W 36
#define SA_TILE_W (64 * SA_W)           // 2304 words
#define SB_TILE_W (128 * SB_W)          // 4608 words
#define SA_TILE_B (SA_TILE_W * 4)
#define SB_TILE_B (SB_TILE_W * 4)
#define MAIN_SMEM_WORDS (2 * SA_TILE_W + 2 * SB_TILE_W + NN + 64 + 4)
#define MAIN_SMEM_BYTES (MAIN_SMEM_WORDS * 4)
#define MAIN_GRID 304                   // 2 per SM on 152 SMs

__global__ void __launch_bounds__(256, 2)
fagcn_main(const int* __restrict__ adj, const float* __restrict__ x0,
           float* __restrict__ out) {
    extern __shared__ __align__(16) uint32_t smw[];
    uint32_t* sA   = smw;                          // [2][64 i][36]
    uint32_t* sB   = smw + 2 * SA_TILE_W;          // [2][128 o][36]
    float*    sAl  = (float*)(smw + 2 * SA_TILE_W + 2 * SB_TILE_W);
    float*    sAr  = sAl + NN;
    int*      sUnit = (int*)(sAr + 64);

    const int tid  = threadIdx.x;
    const int w    = tid >> 5;
    const int lane = tid & 31;
    const int fr   = lane >> 2;
    const int fc   = lane & 3;

    const int jcol = (tid & 15) * 4;
    const int irow = tid >> 4;

    const uint32_t sBb = smem_u32(sB);
    uint32_t bDst[4];
    int      bSrc[4];
#pragma unroll
    for (int e = 0; e < 4; e++) {
        const int inner = (e & 1) * 256 + tid;
        const int blk   = e >> 1;
        const int o     = inner >> 2;
        const int ch    = inner & 3;
        bDst[e] = sBb + (uint32_t)(o * SB_W * 4 + blk * 64 + ch * 16);
        bSrc[e] = blk * 512 + inner;
    }

    const int wm = (w & 1) * 32;
    const int wn = (w >> 1) * 32;

    const uint32_t sAb = smem_u32(sA);
    const uint32_t aAddr0 = sAb + (uint32_t)(wm +  0 + (lane & 7) + 8 * ((lane >> 3) & 1)) * (SA_W * 4)
                          + (uint32_t)(lane >> 4) * 16;
    const uint32_t aAddr1 = sAb + (uint32_t)(wm + 16 + (lane & 7) + 8 * ((lane >> 3) & 1)) * (SA_W * 4)
                          + (uint32_t)(lane >> 4) * 16;
    const uint32_t bAddr  = sBb + (uint32_t)(wn + (lane & 7) + 8 * (lane >> 4)) * (SB_W * 4)
                          + (uint32_t)((lane >> 3) & 1) * 16;

    for (;;) {
        if (tid == 0) *sUnit = atomicAdd(&g_work, 1);
        __syncthreads();
        const int u = *sUnit;
        __syncthreads();
        if (u >= NUNITS) break;

        const int b  = u >> 5;
        const int i0 = (u & 31) * 64;

        for (int i = tid; i < NN; i += 256) sAl[i] = g_al[b * NN + i];
        if (tid < 64) sAr[tid] = g_ar[b * NN + i0 + tid];
        __syncthreads();

        const int* adjp0 = adj + ((size_t)(b * NN + i0 +  0 + irow)) * NN + jcol;
        const int* adjp1 = adj + ((size_t)(b * NN + i0 + 16 + irow)) * NN + jcol;
        const int* adjp2 = adj + ((size_t)(b * NN + i0 + 32 + irow)) * NN + jcol;
        const int* adjp3 = adj + ((size_t)(b * NN + i0 + 48 + irow)) * NN + jcol;
        const float arv0 = sAr[ 0 + irow];
        const float arv1 = sAr[16 + irow];
        const float arv2 = sAr[32 + irow];
        const float arv3 = sAr[48 + irow];
        const uint4* hTb = (const uint4*)(g_hT + ((size_t)b * 64 * 128) * 32);

        float acc[2][4][4];
#pragma unroll
        for (int mt = 0; mt < 2; mt++)
#pragma unroll
            for (int nt = 0; nt < 4; nt++)
#pragma unroll
                for (int c = 0; c < 4; c++) acc[mt][nt][c] = 0.0f;

        int4 pa0, pa1, pa2, pa3;

        auto issueB = [&](int kt, uint32_t dOff) {
            const uint4* src = hTb + (size_t)(2 * kt) * 512;
            CP_ASYNC16(bDst[0] + dOff, (const void*)(src + bSrc[0]));
            CP_ASYNC16(bDst[1] + dOff, (const void*)(src + bSrc[1]));
            CP_ASYNC16(bDst[2] + dOff, (const void*)(src + bSrc[2]));
            CP_ASYNC16(bDst[3] + dOff, (const void*)(src + bSrc[3]));
            CP_COMMIT();
        };
        auto fetchAdj = [&](int jn) {
            pa0 = *(const int4*)(adjp0 + jn);
            pa1 = *(const int4*)(adjp1 + jn);
            pa2 = *(const int4*)(adjp2 + jn);
            pa3 = *(const int4*)(adjp3 + jn);
        };
        auto buildA = [&](uint32_t* An, int j0n) {
            const float4 al4 = *(const float4*)&sAl[j0n + jcol];
            {
                const float t0 = pa0.x ? tanh_fast(arv0 * al4.x) : 0.0f;
                const float t1 = pa0.y ? tanh_fast(arv0 * al4.y) : 0.0f;
                const float t2 = pa0.z ? tanh_fast(arv0 * al4.z) : 0.0f;
                const float t3 = pa0.w ? tanh_fast(arv0 * al4.w) : 0.0f;
                uint2 p; p.x = f2h2(t0, t1); p.y = f2h2(t2, t3);
                *(uint2*)&An[( 0 + irow) * SA_W + (tid & 15) * 2] = p;
            }
            {
                const float t0 = pa1.x ? tanh_fast(arv1 * al4.x) : 0.0f;
                const float t1 = pa1.y ? tanh_fast(arv1 * al4.y) : 0.0f;
                const float t2 = pa1.z ? tanh_fast(arv1 * al4.z) : 0.0f;
                const float t3 = pa1.w ? tanh_fast(arv1 * al4.w) : 0.0f;
                uint2 p; p.x = f2h2(t0, t1); p.y = f2h2(t2, t3);
                *(uint2*)&An[(16 + irow) * SA_W + (tid & 15) * 2] = p;
            }
            {
                const float t0 = pa2.x ? tanh_fast(arv2 * al4.x) : 0.0f;
                const float t1 = pa2.y ? tanh_fast(arv2 * al4.y) : 0.0f;
                const float t2 = pa2.z ? tanh_fast(arv2 * al4.z) : 0.0f;
                const float t3 = pa2.w ? tanh_fast(arv2 * al4.w) : 0.0f;
                uint2 p; p.x = f2h2(t0, t1); p.y = f2h2(t2, t3);
                *(uint2*)&An[(32 + irow) * SA_W + (tid & 15) * 2] = p;
            }
            {
                const float t0 = pa3.x ? tanh_fast(arv3 * al4.x) : 0.0f;
                const float t1 = pa3.y ? tanh_fast(arv3 * al4.y) : 0.0f;
                const float t2 = pa3.z ? tanh_fast(arv3 * al4.z) : 0.0f;
                const float t3 = pa3.w ? tanh_fast(arv3 * al4.w) : 0.0f;
                uint2 p; p.x = f2h2(t0, t1); p.y = f2h2(t2, t3);
                *(uint2*)&An[(48 + irow) * SA_W + (tid & 15) * 2] = p;
            }
        };
        auto doMMA = [&](uint32_t aOff, uint32_t bOff) {
#pragma unroll
            for (int ks = 0; ks < 4; ks++) {
                uint32_t afA[4], afB[4];
                ldmatrix_x4(afA[0], afA[1], afA[2], afA[3], aAddr0 + aOff + ks * 32);
                ldmatrix_x4(afB[0], afB[1], afB[2], afB[3], aAddr1 + aOff + ks * 32);
#pragma unroll
                for (int np = 0; np < 2; np++) {
                    uint32_t b0, b1, b2, b3;
                    ldmatrix_x4(b0, b1, b2, b3, bAddr + bOff + np * (16 * SB_W * 4) + ks * 32);
                    mma_f16(acc[0][2 * np],     afA, b0, b1);
                    mma_f16(acc[0][2 * np + 1], afA, b2, b3);
                    mma_f16(acc[1][2 * np],     afB, b0, b1);
                    mma_f16(acc[1][2 * np + 1], afB, b2, b3);
                }
            }
        };

        issueB(0, 0);
        fetchAdj(0);
        buildA(sA, 0);
        CP_WAIT0();
        __syncthreads();

#pragma unroll 1
        for (int kt2 = 0; kt2 < KT / 2; kt2++) {
            const int kte = 2 * kt2;
            const int kto = kte + 1;

            if (kte < KT - 1) { issueB(kte + 1, SB_TILE_B); fetchAdj((kte + 1) * KC); }
            doMMA(0, 0);
            if (kte < KT - 1) buildA(sA + SA_TILE_W, (kte + 1) * KC);
            CP_WAIT0();
            __syncthreads();

            if (kto < KT - 1) { issueB(kto + 1, 0); fetchAdj((kto + 1) * KC); }
            doMMA(SA_TILE_B, SB_TILE_B);
            if (kto < KT - 1) buildA(sA, (kto + 1) * KC);
            CP_WAIT0();
            __syncthreads();
        }

#pragma unroll
        for (int mt = 0; mt < 2; mt++) {
            const int row = i0 + wm + mt * 16 + fr;
#pragma unroll
            for (int nt = 0; nt < 4; nt++) {
                const int col = wn + nt * 8 + fc * 2;
                const size_t base0 = ((size_t)(b * NN + row)) * CC + col;
                const size_t base1 = base0 + 8 * CC;
                const float2 x00 = *(const float2*)&x0[base0];
                const float2 x01 = *(const float2*)&x0[base1];
                float2 o0, o1;
                o0.x = acc[mt][nt][0] + EPSV * x00.x;
                o0.y = acc[mt][nt][1] + EPSV * x00.y;
                o1.x = acc[mt][nt][2] + EPSV * x01.x;
                o1.y = acc[mt][nt][3] + EPSV * x01.y;
                *(float2*)&out[base0] = o0;
                *(float2*)&out[base1] = o1;
            }
        }
        __syncthreads();
    }
}

extern "C" void kernel_launch(void* const* d_in, const int* in_sizes, int n_in,
                              void* d_out, int out_size) {
    const float* x   = (const float*)d_in[0];
    const float* x0  = (const float*)d_in[1];
    const int*   adj = (const int*)d_in[2];
    const float* W   = (const float*)d_in[3];
    const float* wl  = (const float*)d_in[4];
    const float* wr  = (const float*)d_in[5];
    float* out = (float*)d_out;

    static bool attr_set = false;
    if (!attr_set) {
        cudaFuncSetAttribute(prep_tensor, cudaFuncAttributeMaxDynamicSharedMemorySize,
                             PREP_SMEM_BYTES);
        cudaFuncSetAttribute(fagcn_main, cudaFuncAttributeMaxDynamicSharedMemorySize,
                             MAIN_SMEM_BYTES);
        attr_set = true;
    }

    prep_tensor<<<BATCH * (NN / 64), 256, PREP_SMEM_BYTES>>>(x, W, wl, wr);
    fagcn_main<<<MAIN_GRID, 256, MAIN_SMEM_BYTES>>>(adj, x0, out);
}

// round 14
// speedup vs baseline: 1.1016x; 1.1016x over previous
#include <cuda_runtime.h>
#include <cuda_fp16.h>
#include <cstdint>

#define BATCH 8
#define NN    2048
#define CC    128
#define EPSV  0.1f
#define NUNITS (BATCH * (NN / 64))      // 256 work units (64 i-rows each)

// Scratch (static device globals — no runtime allocation)
__device__ __half g_WT[CC * CC];                  // W^T [o][k] fp16
__device__ __half g_hT[BATCH * 64 * CC * 32];     // blocked hT [b][ktb][o][jj] fp16 (jj=32)
__device__ float  g_al[BATCH * NN];
__device__ float  g_ar[BATCH * NN];
__device__ int    g_work;                          // persistent work counter

// ---------------------------------------------------------------- helpers --
__device__ __forceinline__ float tanh_fast(float x) {
    float y; asm("tanh.approx.f32 %0, %1;" : "=f"(y) : "f"(x)); return y;
}
__device__ __forceinline__ uint32_t f2h2(float lo, float hi) {
    __half2 h = __floats2half2_rn(lo, hi);
    return *(uint32_t*)&h;
}
__device__ __forceinline__ uint32_t smem_u32(const void* p) {
    uint32_t a;
    asm("{ .reg .u64 t; cvta.to.shared.u64 t, %1; cvt.u32.u64 %0, t; }" : "=r"(a) : "l"(p));
    return a;
}
// fp16 MMA m16n8k16
__device__ __forceinline__ void mma_f16(float* d, const uint32_t* a, uint32_t b0, uint32_t b1) {
    asm volatile(
        "mma.sync.aligned.m16n8k16.row.col.f32.f16.f16.f32 "
        "{%0,%1,%2,%3}, {%4,%5,%6,%7}, {%8,%9}, {%0,%1,%2,%3};"
        : "+f"(d[0]), "+f"(d[1]), "+f"(d[2]), "+f"(d[3])
        : "r"(a[0]), "r"(a[1]), "r"(a[2]), "r"(a[3]), "r"(b0), "r"(b1));
}
__device__ __forceinline__ void ldmatrix_x4(uint32_t& r0, uint32_t& r1,
                                            uint32_t& r2, uint32_t& r3, uint32_t addr) {
    asm volatile("ldmatrix.sync.aligned.m8n8.x4.shared.b16 {%0,%1,%2,%3}, [%4];"
                 : "=r"(r0), "=r"(r1), "=r"(r2), "=r"(r3) : "r"(addr));
}
#define CP_ASYNC16(dst, src) \
    asm volatile("cp.async.cg.shared.global [%0], [%1], 16;" :: "r"(dst), "l"(src))
#define CP_COMMIT()  asm volatile("cp.async.commit_group;" ::: "memory")
#define CP_WAIT0()   asm volatile("cp.async.wait_group 0;" ::: "memory")

// ---------------------------------------------------------------------------
// Kernel 0: W [k][o] fp32 -> g_WT [o][k] fp16. Grid 16 x 256 (32x32 tiles).
// Also resets the persistent work counter.
// ---------------------------------------------------------------------------
__global__ void __launch_bounds__(256) convW_kernel(const float* __restrict__ W) {
    __shared__ float st[32][33];
    if (blockIdx.x == 0 && threadIdx.x == 0) g_work = 0;
    const int bx = blockIdx.x & 3;    // k tile
    const int by = blockIdx.x >> 2;   // o tile
    const int r  = threadIdx.x >> 3;
    const int c4 = (threadIdx.x & 7) * 4;

    const float4 v = *(const float4*)&W[(size_t)(bx * 32 + r) * CC + by * 32 + c4];
    st[r][c4 + 0] = v.x; st[r][c4 + 1] = v.y; st[r][c4 + 2] = v.z; st[r][c4 + 3] = v.w;
    __syncthreads();

    uint2 p;
    p.x = f2h2(st[c4 + 0][r], st[c4 + 1][r]);
    p.y = f2h2(st[c4 + 2][r], st[c4 + 3][r]);
    *(uint2*)&g_WT[(size_t)(by * 32 + r) * CC + bx * 32 + c4] = p;
}

// ---------------------------------------------------------------------------
// Kernel 1 (prep): h = x @ W via fp16 mma. 256 blocks x 64 rows, occ 2.
// W^T staged from g_WT via coalesced uint4 (no conflicted scatter).
// Epilogue: alpha_l/alpha_r dots + blocked hT store.
// ---------------------------------------------------------------------------
#define PX_W 68
#define PREP_SMEM_BYTES ((64 * PX_W + 128 * PX_W + 256) * 4)   // 53248 B

__global__ void __launch_bounds__(256, 2)
prep_tensor(const float* __restrict__ x,
            const float* __restrict__ wl, const float* __restrict__ wr) {
    extern __shared__ __align__(16) uint32_t sm[];
    uint32_t* sX  = sm;                        // [64][68] words (x fp16, then h fp16)
    uint32_t* sW  = sm + 64 * PX_W;            // [128 o][68] words (W^T fp16)
    float*    swl = (float*)(sm + 64 * PX_W + 128 * PX_W);
    float*    swr = swl + 128;

    const int tid  = threadIdx.x;
    const int w    = tid >> 5;
    const int lane = tid & 31;
    const int fr   = lane >> 2;
    const int fc   = lane & 3;
    const int b    = blockIdx.x >> 5;
    const int j0   = (blockIdx.x & 31) * 64;
    const int r0   = blockIdx.x * 64;          // == b*NN + j0

    if (tid < 128) { swl[tid] = wl[tid]; swr[tid] = wr[tid]; }

    // stage x tile [64][128] fp32 -> fp16
#pragma unroll
    for (int e = 0; e < 8; e++) {
        const int idx = e * 256 + tid;         // 0..2047 float4
        const int row = idx >> 5;
        const int c4  = (idx & 31) * 4;
        const float4 v = *(const float4*)&x[(size_t)(r0 + row) * CC + c4];
        uint2 p; p.x = f2h2(v.x, v.y); p.y = f2h2(v.z, v.w);
        *(uint2*)&sX[row * PX_W + (idx & 31) * 2] = p;
    }
    // stage W^T [128 o][128 k] fp16: 2048 uint4, coalesced, conflict-free
#pragma unroll
    for (int e = 0; e < 8; e++) {
        const int idx = e * 256 + tid;
        const int o   = idx >> 4;
        const int ks  = idx & 15;
        const uint4 v = ((const uint4*)g_WT)[idx];
        *(uint4*)&sW[o * PX_W + ks * 4] = v;
    }
    __syncthreads();

    // MMA: warp tile 16 rows x 64 cols; wm = (w&3)*16, wn = (w>>2)*64
    const int wm = (w & 3) * 16;
    const int wn = (w >> 2) * 64;
    float acc[8][4];
#pragma unroll
    for (int nt = 0; nt < 8; nt++)
#pragma unroll
        for (int c = 0; c < 4; c++) acc[nt][c] = 0.0f;

#pragma unroll
    for (int ks = 0; ks < 8; ks++) {
        uint32_t af[4];
        const int abase = (wm + fr) * PX_W + ks * 8 + fc;
        af[0] = sX[abase];
        af[1] = sX[abase + 8 * PX_W];
        af[2] = sX[abase + 4];
        af[3] = sX[abase + 8 * PX_W + 4];
#pragma unroll
        for (int nt = 0; nt < 8; nt++) {
            const int bbase = (wn + nt * 8 + fr) * PX_W + ks * 8 + fc;
            mma_f16(acc[nt], af, sW[bbase], sW[bbase + 4]);
        }
    }
    __syncthreads();

    // dump h (fp16) into sX region: [row j][o], word col = o/2
#pragma unroll
    for (int nt = 0; nt < 8; nt++) {
        sX[(wm + fr)     * PX_W + wn / 2 + nt * 4 + fc] = f2h2(acc[nt][0], acc[nt][1]);
        sX[(wm + fr + 8) * PX_W + wn / 2 + nt * 4 + fc] = f2h2(acc[nt][2], acc[nt][3]);
    }
    __syncthreads();

    const __half* sH = (const __half*)sX;      // [j][o] stride 136 halfs

    // blocked hT store: thread -> o = tid>>1, jh = tid&1 (32 j each)
    {
        const int o  = tid >> 1;
        const int jh = tid & 1;
        const int kt = (j0 >> 5) + jh;
        uint32_t wbuf[16];
#pragma unroll
        for (int r2 = 0; r2 < 16; r2++) {
            const int j = jh * 32 + r2 * 2;
            const __half h0 = sH[(size_t)j * 136 + o];
            const __half h1 = sH[(size_t)(j + 1) * 136 + o];
            wbuf[r2] = (uint32_t)__half_as_ushort(h0) | ((uint32_t)__half_as_ushort(h1) << 16);
        }
        uint4* dst = (uint4*)(g_hT + ((size_t)((b * 64 + kt) * 128 + o)) * 32);
        dst[0] = make_uint4(wbuf[0],  wbuf[1],  wbuf[2],  wbuf[3]);
        dst[1] = make_uint4(wbuf[4],  wbuf[5],  wbuf[6],  wbuf[7]);
        dst[2] = make_uint4(wbuf[8],  wbuf[9],  wbuf[10], wbuf[11]);
        dst[3] = make_uint4(wbuf[12], wbuf[13], wbuf[14], wbuf[15]);
    }

    // alpha_l / alpha_r dots: 4 threads per row (oh = tid&3, 32 o's each)
    {
        const int r  = tid >> 2;
        const int oh = tid & 3;
        float pl = 0.0f, pr = 0.0f;
#pragma unroll
        for (int w2 = 0; w2 < 16; w2++) {
            const uint32_t wd = ((const uint32_t*)sH)[r * PX_W + oh * 16 + w2];
            const __half2 hh = *(const __half2*)&wd;
            const float2 f = __half22float2(hh);
            const int o0 = oh * 32 + w2 * 2;
            pl += f.x * swl[o0] + f.y * swl[o0 + 1];
            pr += f.x * swr[o0] + f.y * swr[o0 + 1];
        }
        pl += __shfl_xor_sync(0xffffffffu, pl, 1);
        pr += __shfl_xor_sync(0xffffffffu, pr, 1);
        pl += __shfl_xor_sync(0xffffffffu, pl, 2);
        pr += __shfl_xor_sync(0xffffffffu, pr, 2);
        if (oh == 0) {
            g_al[b * NN + j0 + r] = pl;
            g_ar[b * NN + j0 + r] = pr;
        }
    }
}

// ---------------------------------------------------------------------------
// Kernel 2 (main): persistent work-stealing CTAs. Unit = 64 i x 128 o.
// Warp tile 32 i x 32 o (8 warps). KC=64, double-buffered A (built) and
// B (cp.async). adj: register prefetch fetched at body start. (R12, frozen)
// ---------------------------------------------------------------------------
#define KC 64
#define KT (NN / KC)                    // 32
#define SA_W 36
#define SB_W 36
#define SA_TILE_W (64 * SA_W)           // 2304 words
#define SB_TILE_W (128 * SB_W)          // 4608 words
#define SA_TILE_B (SA_TILE_W * 4)
#define SB_TILE_B (SB_TILE_W * 4)
#define MAIN_SMEM_WORDS (2 * SA_TILE_W + 2 * SB_TILE_W + NN + 64 + 4)
#define MAIN_SMEM_BYTES (MAIN_SMEM_WORDS * 4)
#define MAIN_GRID 304                   // 2 per SM on 152 SMs

__global__ void __launch_bounds__(256, 2)
fagcn_main(const int* __restrict__ adj, const float* __restrict__ x0,
           float* __restrict__ out) {
    extern __shared__ __align__(16) uint32_t smw[];
    uint32_t* sA   = smw;                          // [2][64 i][36]
    uint32_t* sB   = smw + 2 * SA_TILE_W;          // [2][128 o][36]
    float*    sAl  = (float*)(smw + 2 * SA_TILE_W + 2 * SB_TILE_W);
    float*    sAr  = sAl + NN;
    int*      sUnit = (int*)(sAr + 64);

    const int tid  = threadIdx.x;
    const int w    = tid >> 5;
    const int lane = tid & 31;
    const int fr   = lane >> 2;
    const int fc   = lane & 3;

    const int jcol = (tid & 15) * 4;
    const int irow = tid >> 4;

    const uint32_t sBb = smem_u32(sB);
    uint32_t bDst[4];
    int      bSrc[4];
#pragma unroll
    for (int e = 0; e < 4; e++) {
        const int inner = (e & 1) * 256 + tid;
        const int blk   = e >> 1;
        const int o     = inner >> 2;
        const int ch    = inner & 3;
        bDst[e] = sBb + (uint32_t)(o * SB_W * 4 + blk * 64 + ch * 16);
        bSrc[e] = blk * 512 + inner;
    }

    const int wm = (w & 1) * 32;
    const int wn = (w >> 1) * 32;

    const uint32_t sAb = smem_u32(sA);
    const uint32_t aAddr0 = sAb + (uint32_t)(wm +  0 + (lane & 7) + 8 * ((lane >> 3) & 1)) * (SA_W * 4)
                          + (uint32_t)(lane >> 4) * 16;
    const uint32_t aAddr1 = sAb + (uint32_t)(wm + 16 + (lane & 7) + 8 * ((lane >> 3) & 1)) * (SA_W * 4)
                          + (uint32_t)(lane >> 4) * 16;
    const uint32_t bAddr  = sBb + (uint32_t)(wn + (lane & 7) + 8 * (lane >> 4)) * (SB_W * 4)
                          + (uint32_t)((lane >> 3) & 1) * 16;

    for (;;) {
        if (tid == 0) *sUnit = atomicAdd(&g_work, 1);
        __syncthreads();
        const int u = *sUnit;
        __syncthreads();
        if (u >= NUNITS) break;

        const int b  = u >> 5;
        const int i0 = (u & 31) * 64;

        for (int i = tid; i < NN; i += 256) sAl[i] = g_al[b * NN + i];
        if (tid < 64) sAr[tid] = g_ar[b * NN + i0 + tid];
        __syncthreads();

        const int* adjp0 = adj + ((size_t)(b * NN + i0 +  0 + irow)) * NN + jcol;
        const int* adjp1 = adj + ((size_t)(b * NN + i0 + 16 + irow)) * NN + jcol;
        const int* adjp2 = adj + ((size_t)(b * NN + i0 + 32 + irow)) * NN + jcol;
        const int* adjp3 = adj + ((size_t)(b * NN + i0 + 48 + irow)) * NN + jcol;
        const float arv0 = sAr[ 0 + irow];
        const float arv1 = sAr[16 + irow];
        const float arv2 = sAr[32 + irow];
        const float arv3 = sAr[48 + irow];
        const uint4* hTb = (const uint4*)(g_hT + ((size_t)b * 64 * 128) * 32);

        float acc[2][4][4];
#pragma unroll
        for (int mt = 0; mt < 2; mt++)
#pragma unroll
            for (int nt = 0; nt < 4; nt++)
#pragma unroll
                for (int c = 0; c < 4; c++) acc[mt][nt][c] = 0.0f;

        int4 pa0, pa1, pa2, pa3;

        auto issueB = [&](int kt, uint32_t dOff) {
            const uint4* src = hTb + (size_t)(2 * kt) * 512;
            CP_ASYNC16(bDst[0] + dOff, (const void*)(src + bSrc[0]));
            CP_ASYNC16(bDst[1] + dOff, (const void*)(src + bSrc[1]));
            CP_ASYNC16(bDst[2] + dOff, (const void*)(src + bSrc[2]));
            CP_ASYNC16(bDst[3] + dOff, (const void*)(src + bSrc[3]));
            CP_COMMIT();
        };
        auto fetchAdj = [&](int jn) {
            pa0 = *(const int4*)(adjp0 + jn);
            pa1 = *(const int4*)(adjp1 + jn);
            pa2 = *(const int4*)(adjp2 + jn);
            pa3 = *(const int4*)(adjp3 + jn);
        };
        auto buildA = [&](uint32_t* An, int j0n) {
            const float4 al4 = *(const float4*)&sAl[j0n + jcol];
            {
                const float t0 = pa0.x ? tanh_fast(arv0 * al4.x) : 0.0f;
                const float t1 = pa0.y ? tanh_fast(arv0 * al4.y) : 0.0f;
                const float t2 = pa0.z ? tanh_fast(arv0 * al4.z) : 0.0f;
                const float t3 = pa0.w ? tanh_fast(arv0 * al4.w) : 0.0f;
                uint2 p; p.x = f2h2(t0, t1); p.y = f2h2(t2, t3);
                *(uint2*)&An[( 0 + irow) * SA_W + (tid & 15) * 2] = p;
            }
            {
                const float t0 = pa1.x ? tanh_fast(arv1 * al4.x) : 0.0f;
                const float t1 = pa1.y ? tanh_fast(arv1 * al4.y) : 0.0f;
                const float t2 = pa1.z ? tanh_fast(arv1 * al4.z) : 0.0f;
                const float t3 = pa1.w ? tanh_fast(arv1 * al4.w) : 0.0f;
                uint2 p; p.x = f2h2(t0, t1); p.y = f2h2(t2, t3);
                *(uint2*)&An[(16 + irow) * SA_W + (tid & 15) * 2] = p;
            }
            {
                const float t0 = pa2.x ? tanh_fast(arv2 * al4.x) : 0.0f;
                const float t1 = pa2.y ? tanh_fast(arv2 * al4.y) : 0.0f;
                const float t2 = pa2.z ? tanh_fast(arv2 * al4.z) : 0.0f;
                const float t3 = pa2.w ? tanh_fast(arv2 * al4.w) : 0.0f;
                uint2 p; p.x = f2h2(t0, t1); p.y = f2h2(t2, t3);
                *(uint2*)&An[(32 + irow) * SA_W + (tid & 15) * 2] = p;
            }
            {
                const float t0 = pa3.x ? tanh_fast(arv3 * al4.x) : 0.0f;
                const float t1 = pa3.y ? tanh_fast(arv3 * al4.y) : 0.0f;
                const float t2 = pa3.z ? tanh_fast(arv3 * al4.z) : 0.0f;
                const float t3 = pa3.w ? tanh_fast(arv3 * al4.w) : 0.0f;
                uint2 p; p.x = f2h2(t0, t1); p.y = f2h2(t2, t3);
                *(uint2*)&An[(48 + irow) * SA_W + (tid & 15) * 2] = p;
            }
        };
        auto doMMA = [&](uint32_t aOff, uint32_t bOff) {
#pragma unroll
            for (int ks = 0; ks < 4; ks++) {
                uint32_t afA[4], afB[4];
                ldmatrix_x4(afA[0], afA[1], afA[2], afA[3], aAddr0 + aOff + ks * 32);
                ldmatrix_x4(afB[0], afB[1], afB[2], afB[3], aAddr1 + aOff + ks * 32);
#pragma unroll
                for (int np = 0; np < 2; np++) {
                    uint32_t b0, b1, b2, b3;
                    ldmatrix_x4(b0, b1, b2, b3, bAddr + bOff + np * (16 * SB_W * 4) + ks * 32);
                    mma_f16(acc[0][2 * np],     afA, b0, b1);
                    mma_f16(acc[0][2 * np + 1], afA, b2, b3);
                    mma_f16(acc[1][2 * np],     afB, b0, b1);
                    mma_f16(acc[1][2 * np + 1], afB, b2, b3);
                }
            }
        };

        issueB(0, 0);
        fetchAdj(0);
        buildA(sA, 0);
        CP_WAIT0();
        __syncthreads();

#pragma unroll 1
        for (int kt2 = 0; kt2 < KT / 2; kt2++) {
            const int kte = 2 * kt2;
            const int kto = kte + 1;

            if (kte < KT - 1) { issueB(kte + 1, SB_TILE_B); fetchAdj((kte + 1) * KC); }
            doMMA(0, 0);
            if (kte < KT - 1) buildA(sA + SA_TILE_W, (kte + 1) * KC);
            CP_WAIT0();
            __syncthreads();

            if (kto < KT - 1) { issueB(kto + 1, 0); fetchAdj((kto + 1) * KC); }
            doMMA(SA_TILE_B, SB_TILE_B);
            if (kto < KT - 1) buildA(sA, (kto + 1) * KC);
            CP_WAIT0();
            __syncthreads();
        }

#pragma unroll
        for (int mt = 0; mt < 2; mt++) {
            const int row = i0 + wm + mt * 16 + fr;
#pragma unroll
            for (int nt = 0; nt < 4; nt++) {
                const int col = wn + nt * 8 + fc * 2;
                const size_t base0 = ((size_t)(b * NN + row)) * CC + col;
                const size_t base1 = base0 + 8 * CC;
                const float2 x00 = *(const float2*)&x0[base0];
                const float2 x01 = *(const float2*)&x0[base1];
                float2 o0, o1;
                o0.x = acc[mt][nt][0] + EPSV * x00.x;
                o0.y = acc[mt][nt][1] + EPSV * x00.y;
                o1.x = acc[mt][nt][2] + EPSV * x01.x;
                o1.y = acc[mt][nt][3] + EPSV * x01.y;
                *(float2*)&out[base0] = o0;
                *(float2*)&out[base1] = o1;
            }
        }
        __syncthreads();
    }
}

extern "C" void kernel_launch(void* const* d_in, const int* in_sizes, int n_in,
                              void* d_out, int out_size) {
    const float* x   = (const float*)d_in[0];
    const float* x0  = (const float*)d_in[1];
    const int*   adj = (const int*)d_in[2];
    const float* W   = (const float*)d_in[3];
    const float* wl  = (const float*)d_in[4];
    const float* wr  = (const float*)d_in[5];
    float* out = (float*)d_out;

    static bool attr_set = false;
    if (!attr_set) {
        cudaFuncSetAttribute(prep_tensor, cudaFuncAttributeMaxDynamicSharedMemorySize,
                             PREP_SMEM_BYTES);
        cudaFuncSetAttribute(fagcn_main, cudaFuncAttributeMaxDynamicSharedMemorySize,
                             MAIN_SMEM_BYTES);
        attr_set = true;
    }

    convW_kernel<<<16, 256>>>(W);
    prep_tensor<<<BATCH * (NN / 64), 256, PREP_SMEM_BYTES>>>(x, wl, wr);
    fagcn_main<<<MAIN_GRID, 256, MAIN_SMEM_BYTES>>>(adj, x0, out);
}

// round 15
// speedup vs baseline: 1.1298x; 1.0255x over previous
#include <cuda_runtime.h>
#include <cuda_fp16.h>
#include <cstdint>

#define BATCH 8
#define NN    2048
#define CC    128
#define EPSV  0.1f
#define NUNITS (BATCH * (NN / 64))      // 256 work units (64 i-rows each)

// Scratch (static device globals — no runtime allocation)
__device__ __half g_hT[BATCH * 64 * CC * 32];     // blocked hT [b][ktb][o][jj] fp16 (jj=32)
__device__ float  g_al[BATCH * NN];
__device__ float  g_ar[BATCH * NN];
__device__ int    g_work;                          // persistent work counter

// ---------------------------------------------------------------- helpers --
__device__ __forceinline__ float tanh_fast(float x) {
    float y; asm("tanh.approx.f32 %0, %1;" : "=f"(y) : "f"(x)); return y;
}
__device__ __forceinline__ uint32_t f2h2(float lo, float hi) {
    __half2 h = __floats2half2_rn(lo, hi);
    return *(uint32_t*)&h;
}
__device__ __forceinline__ uint32_t smem_u32(const void* p) {
    uint32_t a;
    asm("{ .reg .u64 t; cvta.to.shared.u64 t, %1; cvt.u32.u64 %0, t; }" : "=r"(a) : "l"(p));
    return a;
}
// fp16 MMA m16n8k16
__device__ __forceinline__ void mma_f16(float* d, const uint32_t* a, uint32_t b0, uint32_t b1) {
    asm volatile(
        "mma.sync.aligned.m16n8k16.row.col.f32.f16.f16.f32 "
        "{%0,%1,%2,%3}, {%4,%5,%6,%7}, {%8,%9}, {%0,%1,%2,%3};"
        : "+f"(d[0]), "+f"(d[1]), "+f"(d[2]), "+f"(d[3])
        : "r"(a[0]), "r"(a[1]), "r"(a[2]), "r"(a[3]), "r"(b0), "r"(b1));
}
__device__ __forceinline__ void ldmatrix_x4(uint32_t& r0, uint32_t& r1,
                                            uint32_t& r2, uint32_t& r3, uint32_t addr) {
    asm volatile("ldmatrix.sync.aligned.m8n8.x4.shared.b16 {%0,%1,%2,%3}, [%4];"
                 : "=r"(r0), "=r"(r1), "=r"(r2), "=r"(r3) : "r"(addr));
}
__device__ __forceinline__ void ldmatrix_x4_trans(uint32_t& r0, uint32_t& r1,
                                                  uint32_t& r2, uint32_t& r3, uint32_t addr) {
    asm volatile("ldmatrix.sync.aligned.m8n8.x4.trans.shared.b16 {%0,%1,%2,%3}, [%4];"
                 : "=r"(r0), "=r"(r1), "=r"(r2), "=r"(r3) : "r"(addr));
}
#define CP_ASYNC16(dst, src) \
    asm volatile("cp.async.cg.shared.global [%0], [%1], 16;" :: "r"(dst), "l"(src))
#define CP_COMMIT()  asm volatile("cp.async.commit_group;" ::: "memory")
#define CP_WAIT0()   asm volatile("cp.async.wait_group 0;" ::: "memory")

// ---------------------------------------------------------------------------
// Kernel 1 (prep): h = x @ W via fp16 mma. 256 blocks x 64 rows, occ 2.
// W staged K-MAJOR (straight coalesced fp32->fp16 copy, no transpose);
// B fragments via ldmatrix.x4.trans. Epilogue: alpha dots + blocked hT store.
// Resets the persistent work counter (block 0).
// ---------------------------------------------------------------------------
#define PX_W 68
#define PREP_SMEM_BYTES ((64 * PX_W + 128 * PX_W + 256) * 4)   // 53248 B

__global__ void __launch_bounds__(256, 2)
prep_tensor(const float* __restrict__ x, const float* __restrict__ W,
            const float* __restrict__ wl, const float* __restrict__ wr) {
    extern __shared__ __align__(16) uint32_t sm[];
    uint32_t* sX  = sm;                        // [64 j][68] words (x fp16, then h fp16)
    uint32_t* sW  = sm + 64 * PX_W;            // [128 k][68] words (W fp16, K-MAJOR)
    float*    swl = (float*)(sm + 64 * PX_W + 128 * PX_W);
    float*    swr = swl + 128;

    const int tid  = threadIdx.x;
    const int w    = tid >> 5;
    const int lane = tid & 31;
    const int fr   = lane >> 2;
    const int fc   = lane & 3;
    const int b    = blockIdx.x >> 5;
    const int j0   = (blockIdx.x & 31) * 64;
    const int r0   = blockIdx.x * 64;          // == b*NN + j0

    if (blockIdx.x == 0 && tid == 0) g_work = 0;   // reset persistent counter

    if (tid < 128) { swl[tid] = wl[tid]; swr[tid] = wr[tid]; }

    // stage x tile [64][128] fp32 -> fp16
#pragma unroll
    for (int e = 0; e < 8; e++) {
        const int idx = e * 256 + tid;         // 0..2047 float4
        const int row = idx >> 5;
        const int c4  = (idx & 31) * 4;
        const float4 v = *(const float4*)&x[(size_t)(r0 + row) * CC + c4];
        uint2 p; p.x = f2h2(v.x, v.y); p.y = f2h2(v.z, v.w);
        *(uint2*)&sX[row * PX_W + (idx & 31) * 2] = p;
    }
    // stage W [128 k][128 o] fp32 -> fp16, SAME layout (coalesced, no transpose)
#pragma unroll
    for (int e = 0; e < 16; e++) {
        const int idx = e * 256 + tid;         // 0..4095 float4
        const int k   = idx >> 5;
        const int c4  = (idx & 31) * 4;
        const float4 v = *(const float4*)&W[(size_t)k * CC + c4];
        uint2 p; p.x = f2h2(v.x, v.y); p.y = f2h2(v.z, v.w);
        *(uint2*)&sW[k * PX_W + (idx & 31) * 2] = p;
    }
    __syncthreads();

    // MMA: warp tile 16 rows x 64 cols; wm = (w&3)*16, wn = (w>>2)*64
    const int wm = (w & 3) * 16;
    const int wn = (w >> 2) * 64;
    float acc[8][4];
#pragma unroll
    for (int nt = 0; nt < 8; nt++)
#pragma unroll
        for (int c = 0; c < 4; c++) acc[nt][c] = 0.0f;

    // B fragment base address for ldmatrix.trans:
    // row = ks*16 + (lane&15), col halfs = wn + 8*(lane>>4)
    const uint32_t sWb = smem_u32(sW);
    const uint32_t bTrans = sWb + (uint32_t)((lane & 15) * (PX_W * 4))
                          + (uint32_t)((wn + 8 * (lane >> 4)) * 2);

#pragma unroll
    for (int ks = 0; ks < 8; ks++) {
        uint32_t af[4];
        const int abase = (wm + fr) * PX_W + ks * 8 + fc;
        af[0] = sX[abase];
        af[1] = sX[abase + 8 * PX_W];
        af[2] = sX[abase + 4];
        af[3] = sX[abase + 8 * PX_W + 4];
#pragma unroll
        for (int np = 0; np < 4; np++) {
            uint32_t b0, b1, b2, b3;
            ldmatrix_x4_trans(b0, b1, b2, b3,
                              bTrans + (uint32_t)(ks * 16 * PX_W * 4) + (uint32_t)(np * 32));
            mma_f16(acc[2 * np],     af, b0, b1);
            mma_f16(acc[2 * np + 1], af, b2, b3);
        }
    }
    __syncthreads();

    // dump h (fp16) into sX region: [row j][o], word col = o/2
#pragma unroll
    for (int nt = 0; nt < 8; nt++) {
        sX[(wm + fr)     * PX_W + wn / 2 + nt * 4 + fc] = f2h2(acc[nt][0], acc[nt][1]);
        sX[(wm + fr + 8) * PX_W + wn / 2 + nt * 4 + fc] = f2h2(acc[nt][2], acc[nt][3]);
    }
    __syncthreads();

    const __half* sH = (const __half*)sX;      // [j][o] stride 136 halfs

    // blocked hT store: thread -> o = tid>>1, jh = tid&1 (32 j each)
    {
        const int o  = tid >> 1;
        const int jh = tid & 1;
        const int kt = (j0 >> 5) + jh;
        uint32_t wbuf[16];
#pragma unroll
        for (int r2 = 0; r2 < 16; r2++) {
            const int j = jh * 32 + r2 * 2;
            const __half h0 = sH[(size_t)j * 136 + o];
            const __half h1 = sH[(size_t)(j + 1) * 136 + o];
            wbuf[r2] = (uint32_t)__half_as_ushort(h0) | ((uint32_t)__half_as_ushort(h1) << 16);
        }
        uint4* dst = (uint4*)(g_hT + ((size_t)((b * 64 + kt) * 128 + o)) * 32);
        dst[0] = make_uint4(wbuf[0],  wbuf[1],  wbuf[2],  wbuf[3]);
        dst[1] = make_uint4(wbuf[4],  wbuf[5],  wbuf[6],  wbuf[7]);
        dst[2] = make_uint4(wbuf[8],  wbuf[9],  wbuf[10], wbuf[11]);
        dst[3] = make_uint4(wbuf[12], wbuf[13], wbuf[14], wbuf[15]);
    }

    // alpha_l / alpha_r dots: 4 threads per row (oh = tid&3, 32 o's each)
    {
        const int r  = tid >> 2;
        const int oh = tid & 3;
        float pl = 0.0f, pr = 0.0f;
#pragma unroll
        for (int w2 = 0; w2 < 16; w2++) {
            const uint32_t wd = ((const uint32_t*)sH)[r * PX_W + oh * 16 + w2];
            const __half2 hh = *(const __half2*)&wd;
            const float2 f = __half22float2(hh);
            const int o0 = oh * 32 + w2 * 2;
            pl += f.x * swl[o0] + f.y * swl[o0 + 1];
            pr += f.x * swr[o0] + f.y * swr[o0 + 1];
        }
        pl += __shfl_xor_sync(0xffffffffu, pl, 1);
        pr += __shfl_xor_sync(0xffffffffu, pr, 1);
        pl += __shfl_xor_sync(0xffffffffu, pl, 2);
        pr += __shfl_xor_sync(0xffffffffu, pr, 2);
        if (oh == 0) {
            g_al[b * NN + j0 + r] = pl;
            g_ar[b * NN + j0 + r] = pr;
        }
    }
}

// ---------------------------------------------------------------------------
// Kernel 2 (main): persistent work-stealing CTAs. Unit = 64 i x 128 o.
// Warp tile 32 i x 32 o (8 warps). KC=64, double-buffered A (built) and
// B (cp.async). adj: register prefetch fetched at body start. (R12, frozen)
// ---------------------------------------------------------------------------
#define KC 64
#define KT (NN / KC)                    // 32
#define SA_W 36
#define SB_W 36
#define SA_TILE_W (64 * SA_W)           // 2304 words
#define SB_TILE_W (128 * SB_W)          // 4608 words
#define SA_TILE_B (SA_TILE_W * 4)
#define SB_TILE_B (SB_TILE_W * 4)
#define MAIN_SMEM_WORDS (2 * SA_TILE_W + 2 * SB_TILE_W + NN + 64 + 4)
#define MAIN_SMEM_BYTES (MAIN_SMEM_WORDS * 4)
#define MAIN_GRID 304                   // 2 per SM on 152 SMs

__global__ void __launch_bounds__(256, 2)
fagcn_main(const int* __restrict__ adj, const float* __restrict__ x0,
           float* __restrict__ out) {
    extern __shared__ __align__(16) uint32_t smw[];
    uint32_t* sA   = smw;                          // [2][64 i][36]
    uint32_t* sB   = smw + 2 * SA_TILE_W;          // [2][128 o][36]
    float*    sAl  = (float*)(smw + 2 * SA_TILE_W + 2 * SB_TILE_W);
    float*    sAr  = sAl + NN;
    int*      sUnit = (int*)(sAr + 64);

    const int tid  = threadIdx.x;
    const int w    = tid >> 5;
    const int lane = tid & 31;
    const int fr   = lane >> 2;
    const int fc   = lane & 3;

    const int jcol = (tid & 15) * 4;
    const int irow = tid >> 4;

    const uint32_t sBb = smem_u32(sB);
    uint32_t bDst[4];
    int      bSrc[4];
#pragma unroll
    for (int e = 0; e < 4; e++) {
        const int inner = (e & 1) * 256 + tid;
        const int blk   = e >> 1;
        const int o     = inner >> 2;
        const int ch    = inner & 3;
        bDst[e] = sBb + (uint32_t)(o * SB_W * 4 + blk * 64 + ch * 16);
        bSrc[e] = blk * 512 + inner;
    }

    const int wm = (w & 1) * 32;
    const int wn = (w >> 1) * 32;

    const uint32_t sAb = smem_u32(sA);
    const uint32_t aAddr0 = sAb + (uint32_t)(wm +  0 + (lane & 7) + 8 * ((lane >> 3) & 1)) * (SA_W * 4)
                          + (uint32_t)(lane >> 4) * 16;
    const uint32_t aAddr1 = sAb + (uint32_t)(wm + 16 + (lane & 7) + 8 * ((lane >> 3) & 1)) * (SA_W * 4)
                          + (uint32_t)(lane >> 4) * 16;
    const uint32_t bAddr  = sBb + (uint32_t)(wn + (lane & 7) + 8 * (lane >> 4)) * (SB_W * 4)
                          + (uint32_t)((lane >> 3) & 1) * 16;

    for (;;) {
        if (tid == 0) *sUnit = atomicAdd(&g_work, 1);
        __syncthreads();
        const int u = *sUnit;
        __syncthreads();
        if (u >= NUNITS) break;

        const int b  = u >> 5;
        const int i0 = (u & 31) * 64;

        for (int i = tid; i < NN; i += 256) sAl[i] = g_al[b * NN + i];
        if (tid < 64) sAr[tid] = g_ar[b * NN + i0 + tid];
        __syncthreads();

        const int* adjp0 = adj + ((size_t)(b * NN + i0 +  0 + irow)) * NN + jcol;
        const int* adjp1 = adj + ((size_t)(b * NN + i0 + 16 + irow)) * NN + jcol;
        const int* adjp2 = adj + ((size_t)(b * NN + i0 + 32 + irow)) * NN + jcol;
        const int* adjp3 = adj + ((size_t)(b * NN + i0 + 48 + irow)) * NN + jcol;
        const float arv0 = sAr[ 0 + irow];
        const float arv1 = sAr[16 + irow];
        const float arv2 = sAr[32 + irow];
        const float arv3 = sAr[48 + irow];
        const uint4* hTb = (const uint4*)(g_hT + ((size_t)b * 64 * 128) * 32);

        float acc[2][4][4];
#pragma unroll
        for (int mt = 0; mt < 2; mt++)
#pragma unroll
            for (int nt = 0; nt < 4; nt++)
#pragma unroll
                for (int c = 0; c < 4; c++) acc[mt][nt][c] = 0.0f;

        int4 pa0, pa1, pa2, pa3;

        auto issueB = [&](int kt, uint32_t dOff) {
            const uint4* src = hTb + (size_t)(2 * kt) * 512;
            CP_ASYNC16(bDst[0] + dOff, (const void*)(src + bSrc[0]));
            CP_ASYNC16(bDst[1] + dOff, (const void*)(src + bSrc[1]));
            CP_ASYNC16(bDst[2] + dOff, (const void*)(src + bSrc[2]));
            CP_ASYNC16(bDst[3] + dOff, (const void*)(src + bSrc[3]));
            CP_COMMIT();
        };
        auto fetchAdj = [&](int jn) {
            pa0 = *(const int4*)(adjp0 + jn);
            pa1 = *(const int4*)(adjp1 + jn);
            pa2 = *(const int4*)(adjp2 + jn);
            pa3 = *(const int4*)(adjp3 + jn);
        };
        auto buildA = [&](uint32_t* An, int j0n) {
            const float4 al4 = *(const float4*)&sAl[j0n + jcol];
            {
                const float t0 = pa0.x ? tanh_fast(arv0 * al4.x) : 0.0f;
                const float t1 = pa0.y ? tanh_fast(arv0 * al4.y) : 0.0f;
                const float t2 = pa0.z ? tanh_fast(arv0 * al4.z) : 0.0f;
                const float t3 = pa0.w ? tanh_fast(arv0 * al4.w) : 0.0f;
                uint2 p; p.x = f2h2(t0, t1); p.y = f2h2(t2, t3);
                *(uint2*)&An[( 0 + irow) * SA_W + (tid & 15) * 2] = p;
            }
            {
                const float t0 = pa1.x ? tanh_fast(arv1 * al4.x) : 0.0f;
                const float t1 = pa1.y ? tanh_fast(arv1 * al4.y) : 0.0f;
                const float t2 = pa1.z ? tanh_fast(arv1 * al4.z) : 0.0f;
                const float t3 = pa1.w ? tanh_fast(arv1 * al4.w) : 0.0f;
                uint2 p; p.x = f2h2(t0, t1); p.y = f2h2(t2, t3);
                *(uint2*)&An[(16 + irow) * SA_W + (tid & 15) * 2] = p;
            }
            {
                const float t0 = pa2.x ? tanh_fast(arv2 * al4.x) : 0.0f;
                const float t1 = pa2.y ? tanh_fast(arv2 * al4.y) : 0.0f;
                const float t2 = pa2.z ? tanh_fast(arv2 * al4.z) : 0.0f;
                const float t3 = pa2.w ? tanh_fast(arv2 * al4.w) : 0.0f;
                uint2 p; p.x = f2h2(t0, t1); p.y = f2h2(t2, t3);
                *(uint2*)&An[(32 + irow) * SA_W + (tid & 15) * 2] = p;
            }
            {
                const float t0 = pa3.x ? tanh_fast(arv3 * al4.x) : 0.0f;
                const float t1 = pa3.y ? tanh_fast(arv3 * al4.y) : 0.0f;
                const float t2 = pa3.z ? tanh_fast(arv3 * al4.z) : 0.0f;
                const float t3 = pa3.w ? tanh_fast(arv3 * al4.w) : 0.0f;
                uint2 p; p.x = f2h2(t0, t1); p.y = f2h2(t2, t3);
                *(uint2*)&An[(48 + irow) * SA_W + (tid & 15) * 2] = p;
            }
        };
        auto doMMA = [&](uint32_t aOff, uint32_t bOff) {
#pragma unroll
            for (int ks = 0; ks < 4; ks++) {
                uint32_t afA[4], afB[4];
                ldmatrix_x4(afA[0], afA[1], afA[2], afA[3], aAddr0 + aOff + ks * 32);
                ldmatrix_x4(afB[0], afB[1], afB[2], afB[3], aAddr1 + aOff + ks * 32);
#pragma unroll
                for (int np = 0; np < 2; np++) {
                    uint32_t b0, b1, b2, b3;
                    ldmatrix_x4(b0, b1, b2, b3, bAddr + bOff + np * (16 * SB_W * 4) + ks * 32);
                    mma_f16(acc[0][2 * np],     afA, b0, b1);
                    mma_f16(acc[0][2 * np + 1], afA, b2, b3);
                    mma_f16(acc[1][2 * np],     afB, b0, b1);
                    mma_f16(acc[1][2 * np + 1], afB, b2, b3);
                }
            }
        };

        issueB(0, 0);
        fetchAdj(0);
        buildA(sA, 0);
        CP_WAIT0();
        __syncthreads();

#pragma unroll 1
        for (int kt2 = 0; kt2 < KT / 2; kt2++) {
            const int kte = 2 * kt2;
            const int kto = kte + 1;

            if (kte < KT - 1) { issueB(kte + 1, SB_TILE_B); fetchAdj((kte + 1) * KC); }
            doMMA(0, 0);
            if (kte < KT - 1) buildA(sA + SA_TILE_W, (kte + 1) * KC);
            CP_WAIT0();
            __syncthreads();

            if (kto < KT - 1) { issueB(kto + 1, 0); fetchAdj((kto + 1) * KC); }
            doMMA(SA_TILE_B, SB_TILE_B);
            if (kto < KT - 1) buildA(sA, (kto + 1) * KC);
            CP_WAIT0();
            __syncthreads();
        }

#pragma unroll
        for (int mt = 0; mt < 2; mt++) {
            const int row = i0 + wm + mt * 16 + fr;
#pragma unroll
            for (int nt = 0; nt < 4; nt++) {
                const int col = wn + nt * 8 + fc * 2;
                const size_t base0 = ((size_t)(b * NN + row)) * CC + col;
                const size_t base1 = base0 + 8 * CC;
                const float2 x00 = *(const float2*)&x0[base0];
                const float2 x01 = *(const float2*)&x0[base1];
                float2 o0, o1;
                o0.x = acc[mt][nt][0] + EPSV * x00.x;
                o0.y = acc[mt][nt][1] + EPSV * x00.y;
                o1.x = acc[mt][nt][2] + EPSV * x01.x;
                o1.y = acc[mt][nt][3] + EPSV * x01.y;
                *(float2*)&out[base0] = o0;
                *(float2*)&out[base1] = o1;
            }
        }
        __syncthreads();
    }
}

extern "C" void kernel_launch(void* const* d_in, const int* in_sizes, int n_in,
                              void* d_out, int out_size) {
    const float* x   = (const float*)d_in[0];
    const float* x0  = (const float*)d_in[1];
    const int*   adj = (const int*)d_in[2];
    const float* W   = (const float*)d_in[3];
    const float* wl  = (const float*)d_in[4];
    const float* wr  = (const float*)d_in[5];
    float* out = (float*)d_out;

    static bool attr_set = false;
    if (!attr_set) {
        cudaFuncSetAttribute(prep_tensor, cudaFuncAttributeMaxDynamicSharedMemorySize,
                             PREP_SMEM_BYTES);
        cudaFuncSetAttribute(fagcn_main, cudaFuncAttributeMaxDynamicSharedMemorySize,
                             MAIN_SMEM_BYTES);
        attr_set = true;
    }

    prep_tensor<<<BATCH * (NN / 64), 256, PREP_SMEM_BYTES>>>(x, W, wl, wr);
    fagcn_main<<<MAIN_GRID, 256, MAIN_SMEM_BYTES>>>(adj, x0, out);
}